// round 9
// baseline (speedup 1.0000x reference)
#include <cuda_runtime.h>
#include <cuda_bf16.h>

// Problem constants
#define BB 8
#define SS 2048
#define FF 256
#define HH 8
#define DD 64
#define PROJ 512            // HH*DD
#define NSC 32              // s-chunks (64 rows each)
#define SCH 64              // rows per chunk

// Scratch (device globals — no allocation allowed)
__device__ float g_p[BB * HH * FF];             // p[b][h][f] = Wk_h @ q_last
__device__ float g_cm[BB * HH * NSC * 2];       // per-chunk (max, sumexp)
__device__ float g_yc[BB * NSC * HH * FF];      // unnormalized chunk sums (2MB)
__device__ float g_op[BB * 16 * FF];            // partial outputs per (h,fh)

// Grid barrier state (generation-based: no per-launch reset needed)
__device__ unsigned int g_barc = 0;
__device__ volatile unsigned int g_barg = 0;

__device__ __forceinline__ void grid_barrier() {
    __syncthreads();
    if (threadIdx.x == 0) {
        __threadfence();
        unsigned int gen = g_barg;
        if (atomicAdd(&g_barc, 1) == gridDim.x - 1) {
            g_barc = 0;
            __threadfence();
            g_barg = gen + 1;
        } else {
            while (g_barg == gen) { }
        }
        __threadfence();
    }
    __syncthreads();
}

// Shared memory: phases never overlap within a block -> union
struct SmemPrep {
    float xs[FF];
    float qred[8 * DD];
    float qs[DD];
};
struct SmemFlash {
    float ps[HH * FF];       // 8KB
    float sbuf[HH][SCH];     // 2KB
    float ws[HH][SCH];       // 2KB
    float mh[HH];
};
struct SmemProj {
    float scales[NSC];
    float stats[1];
    float red[3][128];
    float ys[128];
    float ared[8][DD];
    float attn_s[DD];
    float4 red4[7][64];      // 7KB
};
union SmemU {
    SmemPrep prep;
    SmemFlash flash;
    SmemProj proj;
};

// -------------------------------------------------------------------------
// Mega-kernel: 256 blocks x 512 threads, 3 internal grid barriers.
//   P1 (blocks with chunk<8): p[b,h,:] = Wk_h @ (x_last @ Wq_h)
//   P2 (all): flash — scores + local softmax stats + weighted x sums
//   P3 (blocks 0..127): chunk-combine + Wv projection + Wo projection
//   P4 (blocks 0..7):   sum 16 partials + bias -> out
// -------------------------------------------------------------------------
__global__ __launch_bounds__(512, 2)
void k_mega(const float* __restrict__ x,
            const float* __restrict__ Wq,
            const float* __restrict__ Wk,
            const float* __restrict__ Wv,
            const float* __restrict__ Wo,
            const float* __restrict__ bo,
            float* __restrict__ out) {
    __shared__ SmemU sm;
    int blk = blockIdx.x;
    int b = blk >> 5;
    int chunk = blk & 31;
    int t = threadIdx.x;
    int warp = t >> 5, lane = t & 31;

    const float4* xr_base = (const float4*)(x + ((size_t)b * SS + chunk * SCH) * FF);

    // ---------------- Phase 1: p for (b, h=chunk), blocks with chunk<8 ----
    if (chunk < HH) {
        int h = chunk;
        if (t < FF) sm.prep.xs[t] = x[((size_t)b * SS + (SS - 1)) * FF + t];
        __syncthreads();

        {   // q_h[d]: 512 threads = 64 d x 8 f-parts of 32
            int d = t & 63, part = t >> 6;
            const float* wq = Wq + (size_t)(part * 32) * PROJ + h * DD + d;
            const float* xf = sm.prep.xs + part * 32;
            float a = 0.f;
            #pragma unroll
            for (int f = 0; f < 32; ++f) a += xf[f] * wq[(size_t)f * PROJ];
            sm.prep.qred[part * DD + d] = a;
        }
        __syncthreads();
        if (t < DD) {
            float s = 0.f;
            #pragma unroll
            for (int p = 0; p < 8; ++p) s += sm.prep.qred[p * DD + t];
            sm.prep.qs[t] = s;
        }
        __syncthreads();

        float q0 = sm.prep.qs[lane], q1 = sm.prep.qs[32 + lane];
        #pragma unroll 4
        for (int i = 0; i < 16; ++i) {
            int f = warp + 16 * i;
            const float* wk = Wk + (size_t)f * PROJ + h * DD;
            float v = wk[lane] * q0 + wk[32 + lane] * q1;
            #pragma unroll
            for (int o = 16; o; o >>= 1) v += __shfl_xor_sync(0xFFFFFFFFu, v, o);
            if (lane == 0) g_p[(b * HH + h) * FF + f] = v;
        }
        __syncthreads();
    }

    // prefetch phase-A x rows (in flight during barrier spin)
    float4 pa[4], pc[4];
    {
        const float4* xr = xr_base + (size_t)(warp * 4) * 64;
        #pragma unroll
        for (int r = 0; r < 4; ++r) {
            pa[r] = xr[r * 64 + lane];
            pc[r] = xr[r * 64 + 32 + lane];
        }
    }

    grid_barrier();

    // ---------------- Phase 2: flash (all 256 blocks) ---------------------
    for (int i = t; i < HH * FF; i += 512) sm.flash.ps[i] = g_p[b * HH * FF + i];
    __syncthreads();

    {   // scores: warp w -> rows [w*4, w*4+4)
        const float4* ps4 = (const float4*)sm.flash.ps;
        int r0 = warp * 4;
        #pragma unroll
        for (int r = 0; r < 4; ++r) {
            float dot[HH];
            #pragma unroll
            for (int h = 0; h < HH; ++h) {
                float4 qa = ps4[h * 64 + lane];
                float4 qc = ps4[h * 64 + 32 + lane];
                dot[h] = pa[r].x * qa.x + pa[r].y * qa.y + pa[r].z * qa.z + pa[r].w * qa.w
                       + pc[r].x * qc.x + pc[r].y * qc.y + pc[r].z * qc.z + pc[r].w * qc.w;
            }
            #pragma unroll
            for (int h = 0; h < HH; ++h) {
                #pragma unroll
                for (int o = 16; o; o >>= 1)
                    dot[h] += __shfl_xor_sync(0xFFFFFFFFu, dot[h], o);
            }
            if (lane == 0) {
                #pragma unroll
                for (int h = 0; h < HH; ++h)
                    sm.flash.sbuf[h][r0 + r] = dot[h] * 0.125f;
            }
        }
    }
    __syncthreads();

    // local stats: warp h handles head h
    if (warp < HH) {
        int h = warp;
        float v0 = sm.flash.sbuf[h][lane], v1 = sm.flash.sbuf[h][lane + 32];
        float m = fmaxf(v0, v1);
        #pragma unroll
        for (int o = 16; o; o >>= 1) m = fmaxf(m, __shfl_xor_sync(0xFFFFFFFFu, m, o));
        float s = __expf(v0 - m) + __expf(v1 - m);
        #pragma unroll
        for (int o = 16; o; o >>= 1) s += __shfl_xor_sync(0xFFFFFFFFu, s, o);
        if (lane == 0) {
            int idx = ((b * HH + h) * NSC + chunk) * 2;
            g_cm[idx] = m;
            g_cm[idx + 1] = s;
            sm.flash.mh[h] = m;
        }
    }
    __syncthreads();

    {   // unnormalized weights
        int h = t >> 6, s = t & 63;
        sm.flash.ws[h][s] = __expf(sm.flash.sbuf[h][s] - sm.flash.mh[h]);
    }
    __syncthreads();

    {   // weighted sum: thread = (head h = t>>6, f4 = t&63); x hits L1
        int f4 = t & 63, h = t >> 6;
        float4 acc = make_float4(0.f, 0.f, 0.f, 0.f);
        const float* wrow = sm.flash.ws[h];
        #pragma unroll 8
        for (int s = 0; s < SCH; ++s) {
            float4 xv = xr_base[(size_t)s * 64 + f4];
            float w = wrow[s];
            acc.x += w * xv.x; acc.y += w * xv.y; acc.z += w * xv.z; acc.w += w * xv.w;
        }
        float4* out4 = (float4*)(g_yc + ((size_t)(b * NSC + chunk)) * (HH * FF));
        out4[h * 64 + f4] = acc;
    }

    grid_barrier();

    // ---------------- Phase 3: proj, blocks 0..127 ------------------------
    if (blk < BB * HH * 2) {
        int pb = blk >> 4;
        int h = (blk >> 1) & 7;
        int fh = blk & 1;

        if (t < 32) {   // warp 0: global stats + per-chunk scales
            const float* cm = g_cm + (size_t)(pb * HH + h) * NSC * 2;
            float m = cm[t * 2], d = cm[t * 2 + 1];
            float M = m;
            #pragma unroll
            for (int o = 16; o; o >>= 1) M = fmaxf(M, __shfl_xor_sync(0xFFFFFFFFu, M, o));
            float e = __expf(m - M);
            sm.proj.scales[t] = e;
            float ds = d * e;
            #pragma unroll
            for (int o = 16; o; o >>= 1) ds += __shfl_xor_sync(0xFFFFFFFFu, ds, o);
            if (t == 0) sm.proj.stats[0] = 1.f / ds;
        }
        __syncthreads();
        float invD = sm.proj.stats[0];

        {   // y-half: 512 threads = 128 f x 4 chunk-groups of 8
            int f = t & 127, cg = t >> 7;
            const float* pp = g_yc + ((size_t)(pb * NSC + cg * 8) * HH + h) * FF + fh * 128 + f;
            float s = 0.f;
            #pragma unroll
            for (int c = 0; c < 8; ++c)
                s += sm.proj.scales[cg * 8 + c] * pp[(size_t)c * (HH * FF)];
            if (cg > 0) sm.proj.red[cg - 1][f] = s;
            __syncthreads();
            if (cg == 0)
                sm.proj.ys[f] = (s + sm.proj.red[0][f] + sm.proj.red[1][f] + sm.proj.red[2][f]) * invD;
        }
        __syncthreads();

        {   // partial attn: 512 threads = 64 d x 8 f-parts of 16
            int d = t & 63, part = t >> 6;
            const float* wv = Wv + (size_t)(fh * 128 + part * 16) * PROJ + h * DD + d;
            const float* yf = sm.proj.ys + part * 16;
            float a = 0.f;
            #pragma unroll
            for (int f = 0; f < 16; ++f) a += yf[f] * wv[(size_t)f * PROJ];
            sm.proj.ared[part][d] = a;
        }
        __syncthreads();
        if (t < DD) {
            float s = 0.f;
            #pragma unroll
            for (int p = 0; p < 8; ++p) s += sm.proj.ared[p][t];
            sm.proj.attn_s[t] = s;
        }
        __syncthreads();

        {   // Wo projection: 512 threads = 64 j4 x 8 d-parts of 8
            int j4 = t & 63, dp = t >> 6;
            const float4* wo4 = (const float4*)Wo + (size_t)(h * DD + dp * 8) * 64 + j4;
            const float* ad = sm.proj.attn_s + dp * 8;
            float4 acc = make_float4(0.f, 0.f, 0.f, 0.f);
            #pragma unroll
            for (int i = 0; i < 8; ++i) {
                float a = ad[i];
                float4 w = wo4[(size_t)i * 64];
                acc.x += a * w.x; acc.y += a * w.y; acc.z += a * w.z; acc.w += a * w.w;
            }
            if (dp > 0) sm.proj.red4[dp - 1][j4] = acc;
            __syncthreads();
            if (dp == 0) {
                #pragma unroll
                for (int g = 0; g < 7; ++g) {
                    float4 o = sm.proj.red4[g][j4];
                    acc.x += o.x; acc.y += o.y; acc.z += o.z; acc.w += o.w;
                }
                float4* op = (float4*)g_op + (size_t)(pb * 16 + h * 2 + fh) * 64 + j4;
                *op = acc;
            }
        }
    }

    grid_barrier();

    // ---------------- Phase 4: final sum, blocks 0..7 ---------------------
    if (blk < BB && t < FF) {
        const float* pp = g_op + (size_t)blk * 16 * FF + t;
        float s = bo[t];
        #pragma unroll
        for (int p = 0; p < 16; ++p) s += pp[(size_t)p * FF];
        out[(size_t)blk * FF + t] = s;
    }
}

// -------------------------------------------------------------------------
extern "C" void kernel_launch(void* const* d_in, const int* in_sizes, int n_in,
                              void* d_out, int out_size) {
    const float* x  = (const float*)d_in[0];
    const float* Wq = (const float*)d_in[1];
    const float* Wk = (const float*)d_in[2];
    const float* Wv = (const float*)d_in[3];
    const float* Wo = (const float*)d_in[4];
    const float* bo = (const float*)d_in[5];
    float* out = (float*)d_out;

    k_mega<<<BB * NSC, 512>>>(x, Wq, Wk, Wv, Wo, bo, out);
}

// round 10
// speedup vs baseline: 1.1657x; 1.1657x over previous
#include <cuda_runtime.h>
#include <cuda_bf16.h>

// Problem constants
#define BB 8
#define SS 2048
#define FF 256
#define HH 8
#define DD 64
#define PROJ 512            // HH*DD
#define NSC 32              // s-chunks (64 rows each)
#define SCH 64              // rows per chunk
#define GRID 128            // one block per SM, all co-resident

// Scratch (device globals — no allocation allowed)
__device__ float g_p[BB * HH * FF];             // p[b][h][f] = Wk_h @ q_last
__device__ float g_cm[BB * HH * NSC * 2];       // per-chunk (max, sumexp)
__device__ float g_yc[BB * NSC * HH * FF];      // unnormalized chunk sums (2MB)
__device__ float g_op[BB * 16 * FF];            // partial outputs per (h,fh)

// Grid barrier (generation-based; self-resetting, graph-replay safe)
__device__ unsigned int g_barc = 0;
__device__ volatile unsigned int g_barg = 0;

__device__ __forceinline__ void grid_barrier() {
    __syncthreads();
    if (threadIdx.x == 0) {
        __threadfence();
        unsigned int gen = g_barg;
        if (atomicAdd(&g_barc, 1) == GRID - 1) {
            g_barc = 0;
            __threadfence();
            g_barg = gen + 1;
        } else {
            while (g_barg == gen) { }
        }
        __threadfence();   // gpu-scope: flushes L1 so cross-block data is fresh
    }
    __syncthreads();
}

// Phase-local shared memory (phases never overlap -> union)
struct SmemPrep {
    float xs[FF];
    float qred[16][DD];     // 4KB
    float qs[DD];
};
struct SmemFlash {
    float ps[HH * FF];      // 8KB (shared by both halves — depends only on b)
    float sbuf[2][HH][SCH]; // 4KB
    float ws[2][HH][SCH];   // 4KB
    float mh[2][HH];
};
struct SmemProj {
    float scales[NSC];
    float stats[1];
    float red[8][128];      // 4KB
    float ys[128];
    float ared[16][DD];     // 4KB
    float attn_s[DD];
    float ored[4][FF];      // 4KB
};
union SmemU {
    SmemPrep prep;
    SmemFlash flash;
    SmemProj proj;
};

// -------------------------------------------------------------------------
// Mega v2: 128 blocks x 1024 threads, balanced, 3 grid barriers.
//   P1 (blocks 0..63):  p[b,h,:] = Wk_h @ (x_last @ Wq_h)
//   P2 (all 128):       flash over a chunk-PAIR (two 512-thread halves)
//   P3 (all 128):       chunk-combine + Wv proj + Wo proj -> g_op
//   P4 (blocks 0..7):   sum 16 partials + bias -> out
// -------------------------------------------------------------------------
__global__ __launch_bounds__(1024, 1)
void k_mega(const float* __restrict__ x,
            const float* __restrict__ Wq,
            const float* __restrict__ Wk,
            const float* __restrict__ Wv,
            const float* __restrict__ Wo,
            const float* __restrict__ bo,
            float* __restrict__ out) {
    __shared__ SmemU sm;
    int blk = blockIdx.x;
    int t = threadIdx.x;
    int warp = t >> 5, lane = t & 31;

    // ---------------- Phase 1: p for (b = blk>>3, h = blk&7) --------------
    if (blk < BB * HH) {
        int b = blk >> 3, h = blk & 7;
        if (t < FF) sm.prep.xs[t] = x[((size_t)b * SS + (SS - 1)) * FF + t];
        __syncthreads();

        {   // q_h[d]: 1024 threads = 64 d x 16 f-parts of 16
            int d = t & 63, part = t >> 6;
            const float* wq = Wq + (size_t)(part * 16) * PROJ + h * DD + d;
            const float* xf = sm.prep.xs + part * 16;
            float a = 0.f;
            #pragma unroll
            for (int f = 0; f < 16; ++f) a += xf[f] * wq[(size_t)f * PROJ];
            sm.prep.qred[part][d] = a;
        }
        __syncthreads();
        if (t < DD) {
            float s = 0.f;
            #pragma unroll
            for (int p = 0; p < 16; ++p) s += sm.prep.qred[p][t];
            sm.prep.qs[t] = s;
        }
        __syncthreads();

        float q0 = sm.prep.qs[lane], q1 = sm.prep.qs[32 + lane];
        #pragma unroll
        for (int i = 0; i < 8; ++i) {
            int f = warp + 32 * i;
            const float* wk = Wk + (size_t)f * PROJ + h * DD;
            float v = wk[lane] * q0 + wk[32 + lane] * q1;
            #pragma unroll
            for (int o = 16; o; o >>= 1) v += __shfl_xor_sync(0xFFFFFFFFu, v, o);
            if (lane == 0) g_p[(b * HH + h) * FF + f] = v;
        }
    }

    grid_barrier();

    // ---------------- Phase 2: flash over chunk pair -----------------------
    {
        int b = blk >> 4, cpair = blk & 15;
        int half = t >> 9, lt = t & 511;
        int chunk = cpair * 2 + half;
        int hw = warp & 15;   // warp index within half

        const float4* xr_base = (const float4*)(x + ((size_t)b * SS + chunk * SCH) * FF);

        for (int i = t; i < HH * FF; i += 1024) sm.flash.ps[i] = g_p[b * HH * FF + i];
        __syncthreads();

        {   // scores: within each half, warp hw -> rows [hw*4, hw*4+4)
            const float4* ps4 = (const float4*)sm.flash.ps;
            int r0 = hw * 4;
            #pragma unroll
            for (int r = 0; r < 4; ++r) {
                int row = r0 + r;
                float4 a = xr_base[row * 64 + lane];
                float4 c = xr_base[row * 64 + 32 + lane];
                float dot[HH];
                #pragma unroll
                for (int h = 0; h < HH; ++h) {
                    float4 qa = ps4[h * 64 + lane];
                    float4 qc = ps4[h * 64 + 32 + lane];
                    dot[h] = a.x * qa.x + a.y * qa.y + a.z * qa.z + a.w * qa.w
                           + c.x * qc.x + c.y * qc.y + c.z * qc.z + c.w * qc.w;
                }
                #pragma unroll
                for (int h = 0; h < HH; ++h) {
                    #pragma unroll
                    for (int o = 16; o; o >>= 1)
                        dot[h] += __shfl_xor_sync(0xFFFFFFFFu, dot[h], o);
                }
                if (lane == 0) {
                    #pragma unroll
                    for (int h = 0; h < HH; ++h)
                        sm.flash.sbuf[half][h][row] = dot[h] * 0.125f;
                }
            }
        }
        __syncthreads();

        // local stats: warp hw<8 handles head hw of its half's chunk
        if (hw < HH) {
            int h = hw;
            float v0 = sm.flash.sbuf[half][h][lane];
            float v1 = sm.flash.sbuf[half][h][lane + 32];
            float m = fmaxf(v0, v1);
            #pragma unroll
            for (int o = 16; o; o >>= 1) m = fmaxf(m, __shfl_xor_sync(0xFFFFFFFFu, m, o));
            float s = __expf(v0 - m) + __expf(v1 - m);
            #pragma unroll
            for (int o = 16; o; o >>= 1) s += __shfl_xor_sync(0xFFFFFFFFu, s, o);
            if (lane == 0) {
                int idx = ((b * HH + h) * NSC + chunk) * 2;
                g_cm[idx] = m;
                g_cm[idx + 1] = s;
                sm.flash.mh[half][h] = m;
            }
        }
        __syncthreads();

        {   // unnormalized weights: lt covers HH*SCH
            int h = lt >> 6, s = lt & 63;
            sm.flash.ws[half][h][s] = __expf(sm.flash.sbuf[half][h][s] - sm.flash.mh[half][h]);
        }
        __syncthreads();

        {   // weighted sum: lt = (head h, f4); x hits L1
            int f4 = lt & 63, h = lt >> 6;
            float4 acc = make_float4(0.f, 0.f, 0.f, 0.f);
            const float* wrow = sm.flash.ws[half][h];
            #pragma unroll 8
            for (int s = 0; s < SCH; ++s) {
                float4 xv = xr_base[(size_t)s * 64 + f4];
                float w = wrow[s];
                acc.x += w * xv.x; acc.y += w * xv.y; acc.z += w * xv.z; acc.w += w * xv.w;
            }
            float4* out4 = (float4*)(g_yc + ((size_t)(b * NSC + chunk)) * (HH * FF));
            out4[h * 64 + f4] = acc;
        }
    }

    grid_barrier();

    // ---------------- Phase 3: proj (all 128 blocks) -----------------------
    {
        int pb = blk >> 4;
        int h = (blk >> 1) & 7;
        int fh = blk & 1;

        if (t < 32) {   // warp 0: global stats + per-chunk scales
            const float* cm = g_cm + (size_t)(pb * HH + h) * NSC * 2;
            float m = cm[t * 2], d = cm[t * 2 + 1];
            float M = m;
            #pragma unroll
            for (int o = 16; o; o >>= 1) M = fmaxf(M, __shfl_xor_sync(0xFFFFFFFFu, M, o));
            float e = __expf(m - M);
            sm.proj.scales[t] = e;
            float ds = d * e;
            #pragma unroll
            for (int o = 16; o; o >>= 1) ds += __shfl_xor_sync(0xFFFFFFFFu, ds, o);
            if (t == 0) sm.proj.stats[0] = 1.f / ds;
        }
        __syncthreads();
        float invD = sm.proj.stats[0];

        {   // y-half: 1024 threads = 128 f x 8 chunk-groups of 4
            int f = t & 127, cg = t >> 7;
            const float* pp = g_yc + ((size_t)(pb * NSC + cg * 4) * HH + h) * FF + fh * 128 + f;
            float s = 0.f;
            #pragma unroll
            for (int c = 0; c < 4; ++c)
                s += sm.proj.scales[cg * 4 + c] * pp[(size_t)c * (HH * FF)];
            sm.proj.red[cg][f] = s;
        }
        __syncthreads();
        if (t < 128) {
            float s = 0.f;
            #pragma unroll
            for (int g = 0; g < 8; ++g) s += sm.proj.red[g][t];
            sm.proj.ys[t] = s * invD;
        }
        __syncthreads();

        {   // partial attn: 1024 threads = 64 d x 16 f-parts of 8
            int d = t & 63, part = t >> 6;
            const float* wv = Wv + (size_t)(fh * 128 + part * 8) * PROJ + h * DD + d;
            const float* yf = sm.proj.ys + part * 8;
            float a = 0.f;
            #pragma unroll
            for (int f = 0; f < 8; ++f) a += yf[f] * wv[(size_t)f * PROJ];
            sm.proj.ared[part][d] = a;
        }
        __syncthreads();
        if (t < DD) {
            float s = 0.f;
            #pragma unroll
            for (int p = 0; p < 16; ++p) s += sm.proj.ared[p][t];
            sm.proj.attn_s[t] = s;
        }
        __syncthreads();

        {   // Wo projection: 1024 threads = 256 j x 4 d-parts of 16
            int j = t & 255, dp = t >> 8;
            const float* wo = Wo + (size_t)(h * DD + dp * 16) * FF + j;
            const float* ad = sm.proj.attn_s + dp * 16;
            float o = 0.f;
            #pragma unroll
            for (int i = 0; i < 16; ++i) o += ad[i] * wo[(size_t)i * FF];
            sm.proj.ored[dp][j] = o;
        }
        __syncthreads();
        if (t < FF) {
            float s = sm.proj.ored[0][t] + sm.proj.ored[1][t]
                    + sm.proj.ored[2][t] + sm.proj.ored[3][t];
            g_op[(size_t)(pb * 16 + h * 2 + fh) * FF + t] = s;
        }
    }

    grid_barrier();

    // ---------------- Phase 4: final sum (blocks 0..7) ---------------------
    if (blk < BB && t < FF) {
        const float* pp = g_op + (size_t)blk * 16 * FF + t;
        float s = bo[t];
        #pragma unroll
        for (int p = 0; p < 16; ++p) s += pp[(size_t)p * FF];
        out[(size_t)blk * FF + t] = s;
    }
}

// -------------------------------------------------------------------------
extern "C" void kernel_launch(void* const* d_in, const int* in_sizes, int n_in,
                              void* d_out, int out_size) {
    const float* x  = (const float*)d_in[0];
    const float* Wq = (const float*)d_in[1];
    const float* Wk = (const float*)d_in[2];
    const float* Wv = (const float*)d_in[3];
    const float* Wo = (const float*)d_in[4];
    const float* bo = (const float*)d_in[5];
    float* out = (float*)d_out;

    k_mega<<<GRID, 1024>>>(x, Wq, Wk, Wv, Wo, bo, out);
}

// round 11
// speedup vs baseline: 1.3418x; 1.1510x over previous
#include <cuda_runtime.h>
#include <cuda_bf16.h>

// Problem constants
#define BB 8
#define SS 2048
#define FF 256
#define HH 8
#define DD 64
#define PROJ 512            // HH*DD
#define NSC 32              // s-chunks (64 rows each)
#define SCH 64              // rows per chunk
#define GRID 128            // <=148 SMs: all blocks co-resident

// Scratch (device globals — no allocation allowed)
__device__ float g_p[BB * HH * FF];             // p[b][h][f] = Wk_h @ q_last
__device__ float g_cm[BB * HH * NSC * 2];       // per-chunk (max, sumexp)
__device__ float g_yc[BB * NSC * HH * FF];      // unnormalized chunk sums (2MB)
__device__ float g_op[BB * 16 * FF];            // partial outputs per (h,fh)

// Grid barrier (generation-based; self-resetting, graph-replay safe)
__device__ unsigned int g_barc = 0;
__device__ volatile unsigned int g_barg = 0;

__device__ __forceinline__ void grid_barrier() {
    __syncthreads();
    if (threadIdx.x == 0) {
        __threadfence();
        unsigned int gen = g_barg;
        if (atomicAdd(&g_barc, 1) == GRID - 1) {
            g_barc = 0;
            __threadfence();
            g_barg = gen + 1;
        } else {
            while (g_barg == gen) { }
        }
        __threadfence();
    }
    __syncthreads();
}

// Phase-local shared memory (phases never overlap -> union)
struct SmemPrep {
    float xs[FF];
    float qred[8][DD];      // 2KB
    float qs[DD];
};
struct SmemFlash {
    float ps[HH * FF];      // 8KB (depends only on b; load once per block)
    float sbuf[HH][SCH];    // 2KB
    float ws[HH][SCH];      // 2KB
    float mh[HH];
};
struct SmemProj {
    float scales[NSC];
    float stats[1];
    float red[3][128];
    float ys[128];
    float ared[8][DD];
    float attn_s[DD];
    float4 red4[7][64];     // 7KB
};
union SmemU {
    SmemPrep prep;
    SmemFlash flash;
    SmemProj proj;
};

// -------------------------------------------------------------------------
// Mega v3: 128 blocks x 512 threads, up to 128 regs (no spills), 3 barriers.
//   P1 (blocks 0..63):  p[b,h,:] = Wk_h @ (x_last @ Wq_h)
//   P2 (all 128):       flash over a chunk-PAIR, sequential (ps loaded once)
//   P3 (all 128):       chunk-combine + Wv proj + Wo proj -> g_op
//   P4 (blocks 0..7):   sum 16 partials + bias -> out
// -------------------------------------------------------------------------
__global__ __launch_bounds__(512, 1)
void k_mega(const float* __restrict__ x,
            const float* __restrict__ Wq,
            const float* __restrict__ Wk,
            const float* __restrict__ Wv,
            const float* __restrict__ Wo,
            const float* __restrict__ bo,
            float* __restrict__ out) {
    __shared__ SmemU sm;
    int blk = blockIdx.x;
    int t = threadIdx.x;
    int warp = t >> 5, lane = t & 31;

    int fb = blk >> 4;            // batch for flash phase
    int cp = blk & 15;            // chunk pair index

    // ---------------- Phase 1: p for (b = blk>>3, h = blk&7), blocks<64 ----
    if (blk < BB * HH) {
        int b = blk >> 3, h = blk & 7;
        if (t < FF) sm.prep.xs[t] = x[((size_t)b * SS + (SS - 1)) * FF + t];
        __syncthreads();

        {   // q_h[d]: 512 threads = 64 d x 8 f-parts of 32
            int d = t & 63, part = t >> 6;
            const float* wq = Wq + (size_t)(part * 32) * PROJ + h * DD + d;
            const float* xf = sm.prep.xs + part * 32;
            float a = 0.f;
            #pragma unroll
            for (int f = 0; f < 32; ++f) a += xf[f] * wq[(size_t)f * PROJ];
            sm.prep.qred[part][d] = a;
        }
        __syncthreads();
        if (t < DD) {
            float s = 0.f;
            #pragma unroll
            for (int p = 0; p < 8; ++p) s += sm.prep.qred[p][t];
            sm.prep.qs[t] = s;
        }
        __syncthreads();

        float q0 = sm.prep.qs[lane], q1 = sm.prep.qs[32 + lane];
        #pragma unroll 4
        for (int i = 0; i < 16; ++i) {
            int f = warp + 16 * i;
            const float* wk = Wk + (size_t)f * PROJ + h * DD;
            float v = wk[lane] * q0 + wk[32 + lane] * q1;
            #pragma unroll
            for (int o = 16; o; o >>= 1) v += __shfl_xor_sync(0xFFFFFFFFu, v, o);
            if (lane == 0) g_p[(b * HH + h) * FF + f] = v;
        }
        __syncthreads();
    }

    // prefetch first chunk's phase-A rows (in flight during barrier spin)
    float4 pa[4], pc[4];
    {
        const float4* xr = (const float4*)(x + ((size_t)fb * SS + (cp * 2) * SCH) * FF)
                         + (size_t)(warp * 4) * 64;
        #pragma unroll
        for (int r = 0; r < 4; ++r) {
            pa[r] = xr[r * 64 + lane];
            pc[r] = xr[r * 64 + 32 + lane];
        }
    }

    grid_barrier();

    // ---------------- Phase 2: flash over chunk pair (sequential) ----------
    for (int i = t; i < HH * FF; i += 512) sm.flash.ps[i] = g_p[fb * HH * FF + i];
    __syncthreads();

    #pragma unroll
    for (int ci = 0; ci < 2; ++ci) {
        int chunk = cp * 2 + ci;
        const float4* xr_base = (const float4*)(x + ((size_t)fb * SS + chunk * SCH) * FF);

        {   // scores: warp w -> rows [w*4, w*4+4)
            const float4* ps4 = (const float4*)sm.flash.ps;
            int r0 = warp * 4;
            #pragma unroll
            for (int r = 0; r < 4; ++r) {
                float4 a, c;
                if (ci == 0) { a = pa[r]; c = pc[r]; }
                else {
                    a = xr_base[(r0 + r) * 64 + lane];
                    c = xr_base[(r0 + r) * 64 + 32 + lane];
                }
                float dot[HH];
                #pragma unroll
                for (int h = 0; h < HH; ++h) {
                    float4 qa = ps4[h * 64 + lane];
                    float4 qc = ps4[h * 64 + 32 + lane];
                    dot[h] = a.x * qa.x + a.y * qa.y + a.z * qa.z + a.w * qa.w
                           + c.x * qc.x + c.y * qc.y + c.z * qc.z + c.w * qc.w;
                }
                #pragma unroll
                for (int h = 0; h < HH; ++h) {
                    #pragma unroll
                    for (int o = 16; o; o >>= 1)
                        dot[h] += __shfl_xor_sync(0xFFFFFFFFu, dot[h], o);
                }
                if (lane == 0) {
                    #pragma unroll
                    for (int h = 0; h < HH; ++h)
                        sm.flash.sbuf[h][r0 + r] = dot[h] * 0.125f;
                }
            }
        }
        __syncthreads();

        // local stats: warp h handles head h
        if (warp < HH) {
            int h = warp;
            float v0 = sm.flash.sbuf[h][lane], v1 = sm.flash.sbuf[h][lane + 32];
            float m = fmaxf(v0, v1);
            #pragma unroll
            for (int o = 16; o; o >>= 1) m = fmaxf(m, __shfl_xor_sync(0xFFFFFFFFu, m, o));
            float s = __expf(v0 - m) + __expf(v1 - m);
            #pragma unroll
            for (int o = 16; o; o >>= 1) s += __shfl_xor_sync(0xFFFFFFFFu, s, o);
            if (lane == 0) {
                int idx = ((fb * HH + h) * NSC + chunk) * 2;
                g_cm[idx] = m;
                g_cm[idx + 1] = s;
                sm.flash.mh[h] = m;
            }
        }
        __syncthreads();

        {   // unnormalized weights: 512 threads = HH*SCH
            int h = t >> 6, s = t & 63;
            sm.flash.ws[h][s] = __expf(sm.flash.sbuf[h][s] - sm.flash.mh[h]);
        }
        __syncthreads();

        {   // weighted sum: thread = (head h, f4); x hits L1
            int f4 = t & 63, h = t >> 6;
            float4 acc = make_float4(0.f, 0.f, 0.f, 0.f);
            const float* wrow = sm.flash.ws[h];
            #pragma unroll 8
            for (int s = 0; s < SCH; ++s) {
                float4 xv = xr_base[(size_t)s * 64 + f4];
                float w = wrow[s];
                acc.x += w * xv.x; acc.y += w * xv.y; acc.z += w * xv.z; acc.w += w * xv.w;
            }
            float4* out4 = (float4*)(g_yc + ((size_t)(fb * NSC + chunk)) * (HH * FF));
            out4[h * 64 + f4] = acc;
        }
        __syncthreads();
    }

    grid_barrier();

    // ---------------- Phase 3: proj (all 128 blocks) -----------------------
    {
        int pb = blk >> 4;
        int h = (blk >> 1) & 7;
        int fh = blk & 1;

        if (t < 32) {   // warp 0: global stats + per-chunk scales
            const float* cm = g_cm + (size_t)(pb * HH + h) * NSC * 2;
            float m = cm[t * 2], d = cm[t * 2 + 1];
            float M = m;
            #pragma unroll
            for (int o = 16; o; o >>= 1) M = fmaxf(M, __shfl_xor_sync(0xFFFFFFFFu, M, o));
            float e = __expf(m - M);
            sm.proj.scales[t] = e;
            float ds = d * e;
            #pragma unroll
            for (int o = 16; o; o >>= 1) ds += __shfl_xor_sync(0xFFFFFFFFu, ds, o);
            if (t == 0) sm.proj.stats[0] = 1.f / ds;
        }
        __syncthreads();
        float invD = sm.proj.stats[0];

        {   // y-half: 512 threads = 128 f x 4 chunk-groups of 8
            int f = t & 127, cg = t >> 7;
            const float* pp = g_yc + ((size_t)(pb * NSC + cg * 8) * HH + h) * FF + fh * 128 + f;
            float s = 0.f;
            #pragma unroll
            for (int c = 0; c < 8; ++c)
                s += sm.proj.scales[cg * 8 + c] * pp[(size_t)c * (HH * FF)];
            if (cg > 0) sm.proj.red[cg - 1][f] = s;
            __syncthreads();
            if (cg == 0)
                sm.proj.ys[f] = (s + sm.proj.red[0][f] + sm.proj.red[1][f] + sm.proj.red[2][f]) * invD;
        }
        __syncthreads();

        {   // partial attn: 512 threads = 64 d x 8 f-parts of 16
            int d = t & 63, part = t >> 6;
            const float* wv = Wv + (size_t)(fh * 128 + part * 16) * PROJ + h * DD + d;
            const float* yf = sm.proj.ys + part * 16;
            float a = 0.f;
            #pragma unroll
            for (int f = 0; f < 16; ++f) a += yf[f] * wv[(size_t)f * PROJ];
            sm.proj.ared[part][d] = a;
        }
        __syncthreads();
        if (t < DD) {
            float s = 0.f;
            #pragma unroll
            for (int p = 0; p < 8; ++p) s += sm.proj.ared[p][t];
            sm.proj.attn_s[t] = s;
        }
        __syncthreads();

        {   // Wo projection: 512 threads = 64 j4 x 8 d-parts of 8
            int j4 = t & 63, dp = t >> 6;
            const float4* wo4 = (const float4*)Wo + (size_t)(h * DD + dp * 8) * 64 + j4;
            const float* ad = sm.proj.attn_s + dp * 8;
            float4 acc = make_float4(0.f, 0.f, 0.f, 0.f);
            #pragma unroll
            for (int i = 0; i < 8; ++i) {
                float a = ad[i];
                float4 w = wo4[(size_t)i * 64];
                acc.x += a * w.x; acc.y += a * w.y; acc.z += a * w.z; acc.w += a * w.w;
            }
            if (dp > 0) sm.proj.red4[dp - 1][j4] = acc;
            __syncthreads();
            if (dp == 0) {
                #pragma unroll
                for (int g = 0; g < 7; ++g) {
                    float4 o = sm.proj.red4[g][j4];
                    acc.x += o.x; acc.y += o.y; acc.z += o.z; acc.w += o.w;
                }
                float4* op = (float4*)g_op + (size_t)(pb * 16 + h * 2 + fh) * 64 + j4;
                *op = acc;
            }
        }
    }

    grid_barrier();

    // ---------------- Phase 4: final sum (blocks 0..7) ---------------------
    if (blk < BB && t < FF) {
        const float* pp = g_op + (size_t)blk * 16 * FF + t;
        float s = bo[t];
        #pragma unroll
        for (int p = 0; p < 16; ++p) s += pp[(size_t)p * FF];
        out[(size_t)blk * FF + t] = s;
    }
}

// -------------------------------------------------------------------------
extern "C" void kernel_launch(void* const* d_in, const int* in_sizes, int n_in,
                              void* d_out, int out_size) {
    const float* x  = (const float*)d_in[0];
    const float* Wq = (const float*)d_in[1];
    const float* Wk = (const float*)d_in[2];
    const float* Wv = (const float*)d_in[3];
    const float* Wo = (const float*)d_in[4];
    const float* bo = (const float*)d_in[5];
    float* out = (float*)d_out;

    k_mega<<<GRID, 512>>>(x, Wq, Wk, Wv, Wo, bo, out);
}

// round 12
// speedup vs baseline: 1.5744x; 1.1734x over previous
#include <cuda_runtime.h>
#include <cuda_bf16.h>

// Problem constants
#define BB 8
#define SS 2048
#define FF 256
#define HH 8
#define DD 64
#define PROJ 512            // HH*DD
#define NSC 32              // s-chunks (64 rows each)
#define SCH 64              // rows per chunk

// Scratch (device globals — no allocation allowed)
__device__ float g_p[BB * HH * FF];             // p[b][h][f] = Wk_h @ q_last
__device__ float g_cm[BB * HH * NSC * 2];       // per-chunk (max, sumexp)
__device__ float g_yc[BB * NSC * HH * FF];      // unnormalized chunk sums (2MB)
__device__ float g_attnp[2 * BB * PROJ];        // partial attn (f-halves)

// -------------------------------------------------------------------------
// K1: per (b,h): q_h = x[b,S-1,:] @ Wq[:,h*64:+64]; p[b,h,f] = Wk[f,h*64:].q_h
// grid: 64 blocks, 512 threads
// -------------------------------------------------------------------------
__global__ void k_prep(const float* __restrict__ x,
                       const float* __restrict__ Wq,
                       const float* __restrict__ Wk) {
    int blk = blockIdx.x;
    int b = blk >> 3, h = blk & 7;
    int t = threadIdx.x;
    __shared__ float xs[FF];
    __shared__ float qred[8][DD];
    __shared__ float qs[DD];
    __shared__ float qp[2][FF];

    if (t < FF) xs[t] = x[((size_t)b * SS + (SS - 1)) * FF + t];
    __syncthreads();

    {   // q_h[d]: 512 threads = 64 d x 8 f-parts of 32; batched loads (MLP 16)
        int d = t & 63, part = t >> 6;
        const float* wq = Wq + (size_t)(part * 32) * PROJ + h * DD + d;
        const float* xf = xs + part * 32;
        float a = 0.f;
        #pragma unroll
        for (int g = 0; g < 2; ++g) {
            float w[16];
            #pragma unroll
            for (int i = 0; i < 16; ++i) w[i] = wq[(size_t)(g * 16 + i) * PROJ];
            #pragma unroll
            for (int i = 0; i < 16; ++i) a += xf[g * 16 + i] * w[i];
        }
        qred[part][d] = a;
    }
    __syncthreads();
    if (t < DD) {
        float s = 0.f;
        #pragma unroll
        for (int p = 0; p < 8; ++p) s += qred[p][t];
        qs[t] = s;
    }
    __syncthreads();

    {   // p[f]: shuffle-free. 512 threads = 256 f x 2 d-halves of 32.
        // Each thread reads its own contiguous 128B of Wk (8 float4, MLP 8).
        int f = t & 255, dh = t >> 8;
        const float4* wk4 = (const float4*)(Wk + (size_t)f * PROJ + h * DD + dh * 32);
        const float4* q4 = (const float4*)(qs + dh * 32);
        float4 w[8];
        #pragma unroll
        for (int i = 0; i < 8; ++i) w[i] = wk4[i];
        float a = 0.f;
        #pragma unroll
        for (int i = 0; i < 8; ++i) {
            float4 q = q4[i];
            a += w[i].x * q.x + w[i].y * q.y + w[i].z * q.z + w[i].w * q.w;
        }
        qp[dh][f] = a;
    }
    __syncthreads();
    if (t < FF) g_p[(b * HH + h) * FF + t] = qp[0][t] + qp[1][t];
}

// -------------------------------------------------------------------------
// K2: flash pass — one read of x. Per (b, 64-row chunk):
//   Phase A: scores; local stats (m_c, d_c) -> g_cm; ws = exp(sc - m_c)
//   Phase B: yc[h][f] = sum_s ws[h][s] * x[s][f]  (x re-read from L1)
// grid: BB*NSC = 256 blocks, 256 threads
// -------------------------------------------------------------------------
__global__ void k_flash(const float* __restrict__ x) {
    int blk = blockIdx.x;
    int b = blk >> 5;
    int chunk = blk & 31;
    int t = threadIdx.x;
    int warp = t >> 5, lane = t & 31;
    __shared__ float ps[HH * FF];       // 8KB
    __shared__ float sbuf[HH][SCH];     // 2KB
    __shared__ float ws[HH][SCH];       // 2KB
    __shared__ float mh[HH];

    for (int i = t; i < HH * FF; i += 256) ps[i] = g_p[b * HH * FF + i];
    __syncthreads();

    const float4* ps4 = (const float4*)ps;
    const float4* xr_base = (const float4*)(x + ((size_t)b * SS + chunk * SCH) * FF);

    // ---- Phase A: scores ----
    #pragma unroll
    for (int it = 0; it < 2; ++it) {
        int r0 = it * 32 + warp * 4;
        const float4* xr = xr_base + (size_t)r0 * 64;

        float4 a[4], c[4];
        #pragma unroll
        for (int r = 0; r < 4; ++r) {
            a[r] = xr[r * 64 + lane];
            c[r] = xr[r * 64 + 32 + lane];
        }

        #pragma unroll
        for (int r = 0; r < 4; ++r) {
            float dot[HH];
            #pragma unroll
            for (int h = 0; h < HH; ++h) {
                float4 pa = ps4[h * 64 + lane];
                float4 pc = ps4[h * 64 + 32 + lane];
                dot[h] = a[r].x * pa.x + a[r].y * pa.y + a[r].z * pa.z + a[r].w * pa.w
                       + c[r].x * pc.x + c[r].y * pc.y + c[r].z * pc.z + c[r].w * pc.w;
            }
            #pragma unroll
            for (int h = 0; h < HH; ++h) {
                #pragma unroll
                for (int o = 16; o; o >>= 1)
                    dot[h] += __shfl_xor_sync(0xFFFFFFFFu, dot[h], o);
            }
            if (lane == 0) {
                #pragma unroll
                for (int h = 0; h < HH; ++h)
                    sbuf[h][r0 + r] = dot[h] * 0.125f;
            }
        }
    }
    __syncthreads();

    // ---- local stats: warp h handles head h ----
    if (warp < HH) {
        int h = warp;
        float v0 = sbuf[h][lane], v1 = sbuf[h][lane + 32];
        float m = fmaxf(v0, v1);
        #pragma unroll
        for (int o = 16; o; o >>= 1) m = fmaxf(m, __shfl_xor_sync(0xFFFFFFFFu, m, o));
        float s = __expf(v0 - m) + __expf(v1 - m);
        #pragma unroll
        for (int o = 16; o; o >>= 1) s += __shfl_xor_sync(0xFFFFFFFFu, s, o);
        if (lane == 0) {
            int idx = ((b * HH + h) * NSC + chunk) * 2;
            g_cm[idx] = m;
            g_cm[idx + 1] = s;
            mh[h] = m;
        }
    }
    __syncthreads();

    // ---- unnormalized weights ----
    #pragma unroll
    for (int i = 0; i < 2; ++i) {
        int e = t + i * 256;
        int h = e >> 6, s = e & 63;
        ws[h][s] = __expf(sbuf[h][s] - mh[h]);
    }
    __syncthreads();

    // ---- Phase B: weighted sum (x hits L1); head-pair per thread ----
    int f4 = t & 63, hp = t >> 6;
    int h0 = hp * 2;
    float4 a0 = make_float4(0.f, 0.f, 0.f, 0.f);
    float4 a1 = make_float4(0.f, 0.f, 0.f, 0.f);

    #pragma unroll 4
    for (int s = 0; s < SCH; ++s) {
        float4 xv = xr_base[(size_t)s * 64 + f4];
        float w0 = ws[h0][s], w1 = ws[h0 + 1][s];
        a0.x += w0 * xv.x; a0.y += w0 * xv.y; a0.z += w0 * xv.z; a0.w += w0 * xv.w;
        a1.x += w1 * xv.x; a1.y += w1 * xv.y; a1.z += w1 * xv.z; a1.w += w1 * xv.w;
    }

    float4* out4 = (float4*)(g_yc + ((size_t)(b * NSC + chunk)) * (HH * FF));
    out4[h0 * 64 + f4] = a0;
    out4[(h0 + 1) * 64 + f4] = a1;
}

// -------------------------------------------------------------------------
// K3: per (b,h,f-half): y[f] = (sum_c exp(m_c-M) yc[c][f]) / D; then
//     partial attn over this f-half: attnp = y_half @ Wv_half
// grid: BB*HH*2 = 128 blocks, 512 threads
// -------------------------------------------------------------------------
__global__ void k_attn(const float* __restrict__ Wv) {
    int blk = blockIdx.x;
    int b = blk >> 4;
    int h = (blk >> 1) & 7;
    int fh = blk & 1;
    int t = threadIdx.x;
    __shared__ float scales[NSC];
    __shared__ float stats[2];          // invD
    __shared__ float red[3][128];
    __shared__ float ys[128];
    __shared__ float ared[8][DD];

    if (t < 32) {   // warp 0: global stats + per-chunk scales
        const float* cm = g_cm + (size_t)(b * HH + h) * NSC * 2;
        float m = cm[t * 2], d = cm[t * 2 + 1];
        float M = m;
        #pragma unroll
        for (int o = 16; o; o >>= 1) M = fmaxf(M, __shfl_xor_sync(0xFFFFFFFFu, M, o));
        float e = __expf(m - M);
        scales[t] = e;
        float ds = d * e;
        #pragma unroll
        for (int o = 16; o; o >>= 1) ds += __shfl_xor_sync(0xFFFFFFFFu, ds, o);
        if (t == 0) stats[1] = 1.f / ds;
    }
    __syncthreads();
    float invD = stats[1];

    {   // y-half: 512 threads = 128 f x 4 chunk-groups of 8; batched loads
        int f = t & 127, cg = t >> 7;
        const float* pp = g_yc + ((size_t)(b * NSC + cg * 8) * HH + h) * FF + fh * 128 + f;
        float v[8];
        #pragma unroll
        for (int c = 0; c < 8; ++c) v[c] = pp[(size_t)c * (HH * FF)];
        float s = 0.f;
        #pragma unroll
        for (int c = 0; c < 8; ++c) s += scales[cg * 8 + c] * v[c];
        if (cg > 0) red[cg - 1][f] = s;
        __syncthreads();
        if (cg == 0) ys[f] = (s + red[0][f] + red[1][f] + red[2][f]) * invD;
    }
    __syncthreads();

    {   // partial attn: 512 threads = 64 d x 8 f-parts of 16; batched loads
        int d = t & 63, part = t >> 6;
        const float* wv = Wv + (size_t)(fh * 128 + part * 16) * PROJ + h * DD + d;
        const float* yf = ys + part * 16;
        float w[16];
        #pragma unroll
        for (int f = 0; f < 16; ++f) w[f] = wv[(size_t)f * PROJ];
        float a = 0.f;
        #pragma unroll
        for (int f = 0; f < 16; ++f) a += yf[f] * w[f];
        ared[part][d] = a;
    }
    __syncthreads();
    if (t < DD) {
        float s = 0.f;
        #pragma unroll
        for (int p = 0; p < 8; ++p) s += ared[p][t];
        g_attnp[(size_t)fh * (BB * PROJ) + b * PROJ + h * DD + t] = s;
    }
}

// -------------------------------------------------------------------------
// K4: out[b,j] = sum_c attn[b,c] * Wo[c,j] + bo[j]
// grid: BB*8 = 64 blocks (32 j each), 256 threads
// thread: jl = t&7 (4 j via float4), cpart = t>>3 (32 parts x 16 c)
// EXPLICIT 16-float4 prefetch to force MLP=16 (regs ~90).
// -------------------------------------------------------------------------
__global__ void k_final(const float* __restrict__ Wo,
                        const float* __restrict__ bo,
                        float* __restrict__ out) {
    int blk = blockIdx.x;
    int b = blk >> 3, jblk = blk & 7;
    int t = threadIdx.x;
    __shared__ float as[PROJ];
    __shared__ float4 red[32][8];     // 4KB
    __shared__ float4 red2[8][8];     // 1KB

    #pragma unroll
    for (int i = 0; i < 2; ++i) {
        int c = t + i * 256;
        as[c] = g_attnp[b * PROJ + c] + g_attnp[BB * PROJ + b * PROJ + c];
    }
    __syncthreads();

    int jl = t & 7, cpart = t >> 3;
    int c0 = cpart * 16;
    const float4* wo4 = (const float4*)Wo + jblk * 8 + jl + (size_t)c0 * 64;

    // prefetch ALL 16 rows first (64 registers of data, MLP 16)
    float4 w[16];
    #pragma unroll
    for (int c = 0; c < 16; ++c) w[c] = wo4[(size_t)c * 64];

    float4 acc = make_float4(0.f, 0.f, 0.f, 0.f);
    #pragma unroll
    for (int c = 0; c < 16; ++c) {
        float a = as[c0 + c];
        acc.x += a * w[c].x; acc.y += a * w[c].y;
        acc.z += a * w[c].z; acc.w += a * w[c].w;
    }
    red[cpart][jl] = acc;
    __syncthreads();

    if (t < 64) {   // stage 1: group g sums 4 cparts
        int l = t & 7, g = t >> 3;
        float4 s = red[g * 4][l];
        #pragma unroll
        for (int p = 1; p < 4; ++p) {
            float4 o = red[g * 4 + p][l];
            s.x += o.x; s.y += o.y; s.z += o.z; s.w += o.w;
        }
        red2[g][l] = s;
    }
    __syncthreads();

    if (t < 8) {    // stage 2: sum 8 groups, add bias, store float4
        float4 s = red2[0][t];
        #pragma unroll
        for (int g = 1; g < 8; ++g) {
            float4 o = red2[g][t];
            s.x += o.x; s.y += o.y; s.z += o.z; s.w += o.w;
        }
        int j = jblk * 32 + t * 4;
        float4 bv = *(const float4*)(bo + j);
        s.x += bv.x; s.y += bv.y; s.z += bv.z; s.w += bv.w;
        *(float4*)(out + (size_t)b * FF + j) = s;
    }
}

// -------------------------------------------------------------------------
extern "C" void kernel_launch(void* const* d_in, const int* in_sizes, int n_in,
                              void* d_out, int out_size) {
    const float* x  = (const float*)d_in[0];
    const float* Wq = (const float*)d_in[1];
    const float* Wk = (const float*)d_in[2];
    const float* Wv = (const float*)d_in[3];
    const float* Wo = (const float*)d_in[4];
    const float* bo = (const float*)d_in[5];
    float* out = (float*)d_out;

    k_prep<<<BB * HH, 512>>>(x, Wq, Wk);
    k_flash<<<BB * NSC, 256>>>(x);
    k_attn<<<BB * HH * 2, 512>>>(Wv);
    k_final<<<BB * 8, 256>>>(Wo, bo, out);
}